// round 3
// baseline (speedup 1.0000x reference)
#include <cuda_runtime.h>
#include <math.h>

#define D 128

// ---------------------------------------------------------------------------
// Scratch (device globals — no dynamic allocation allowed)
// ---------------------------------------------------------------------------
#define MAXROWS 716800          // >= NE+NF+NA+NF+NE = 700000
#define MAXE    2200000         // >= 5 * 400000
__device__ float    g_agg[(size_t)MAXROWS * D];   // mean-aggregated features
__device__ unsigned g_B[5 * 2 * D * D];           // tf32 bits: [t][wl|wr][n][k]
__device__ int      g_deg[MAXROWS];               // degree histogram
__device__ int      g_rowStart[MAXROWS + 1];      // CSR row offsets
__device__ int      g_head[MAXROWS];              // running fill cursor
__device__ int      g_eSrc[MAXE];                 // CSR: src index per edge
__device__ int      g_blockSums[1025];            // scan temp

// ---------------------------------------------------------------------------
// prep: convert all 5 wl / wr matrices to tf32 bits. Layout [t][side][n*128+k]
// ---------------------------------------------------------------------------
struct PrepParams { const float* wl[5]; const float* wr[5]; };

__global__ void prep_kernel(PrepParams p) {
    int i = blockIdx.x * blockDim.x + threadIdx.x;      // 0 .. 163839
    int t = i >> 15;
    int r = i & 32767;
    int side = r >> 14;
    int idx = r & 16383;
    float v = (side ? p.wr[t] : p.wl[t])[idx];
    unsigned u;
    asm("cvt.rna.tf32.f32 %0, %1;" : "=r"(u) : "f"(v));
    g_B[i] = u;
}

// ---------------------------------------------------------------------------
// CSR build: histogram -> scan (3 pass) -> fill
// ---------------------------------------------------------------------------
struct EdgeParams {
    const int* si[5];
    const int* di[5];
    int cntOff[5];      // row offset of each type's dst segment
    int ePrefix[6];     // cumulative edge counts
};

__global__ void hist_kernel(EdgeParams p) {
    int i = blockIdx.x * blockDim.x + threadIdx.x;
    if (i >= p.ePrefix[5]) return;
    int t = 0;
    while (i >= p.ePrefix[t + 1]) t++;
    int e = i - p.ePrefix[t];
    atomicAdd(&g_deg[p.cntOff[t] + p.di[t][e]], 1);
}

// pass1: per-block (4096 elems) exclusive scan + block totals
__global__ void scan1_kernel(int R) {
    __shared__ int wsumS[32];
    __shared__ int blkTotS;
    int tidx = threadIdx.x, lane = tidx & 31, w = tidx >> 5;
    int base = blockIdx.x * 4096 + tidx * 4;
    int v0 = (base + 0 < R) ? g_deg[base + 0] : 0;
    int v1 = (base + 1 < R) ? g_deg[base + 1] : 0;
    int v2 = (base + 2 < R) ? g_deg[base + 2] : 0;
    int v3 = (base + 3 < R) ? g_deg[base + 3] : 0;
    int tsum = v0 + v1 + v2 + v3;
    int inc = tsum;
#pragma unroll
    for (int off = 1; off < 32; off <<= 1) {
        int n = __shfl_up_sync(0xffffffffu, inc, off);
        if (lane >= off) inc += n;
    }
    if (lane == 31) wsumS[w] = inc;
    __syncthreads();
    if (w == 0) {
        int x = wsumS[lane];
        int incw = x;
#pragma unroll
        for (int off = 1; off < 32; off <<= 1) {
            int n = __shfl_up_sync(0xffffffffu, incw, off);
            if (lane >= off) incw += n;
        }
        wsumS[lane] = incw - x;            // exclusive
        if (lane == 31) blkTotS = incw;
    }
    __syncthreads();
    int excl = inc - tsum + wsumS[w];
    if (base + 0 < R) g_rowStart[base + 0] = excl;
    excl += v0;
    if (base + 1 < R) g_rowStart[base + 1] = excl;
    excl += v1;
    if (base + 2 < R) g_rowStart[base + 2] = excl;
    excl += v2;
    if (base + 3 < R) g_rowStart[base + 3] = excl;
    if (tidx == 0) g_blockSums[blockIdx.x] = blkTotS;
}

// pass2: serial exclusive scan of block totals (nb ~ 171, trivial)
__global__ void scan2_kernel(int nb) {
    if (threadIdx.x == 0 && blockIdx.x == 0) {
        int s = 0;
        for (int i = 0; i < nb; i++) {
            int t = g_blockSums[i];
            g_blockSums[i] = s;
            s += t;
        }
        g_blockSums[nb] = s;
    }
}

// pass3: add block offsets; also seed the fill cursors
__global__ void scan3_kernel(int R, int nb) {
    int i = blockIdx.x * blockDim.x + threadIdx.x;
    if (i < R) {
        int v = g_rowStart[i] + g_blockSums[i >> 12];
        g_rowStart[i] = v;
        g_head[i] = v;
    }
    if (i == R) g_rowStart[R] = g_blockSums[nb];
}

__global__ void fill_kernel(EdgeParams p) {
    int i = blockIdx.x * blockDim.x + threadIdx.x;
    if (i >= p.ePrefix[5]) return;
    int t = 0;
    while (i >= p.ePrefix[t + 1]) t++;
    int e = i - p.ePrefix[t];
    int s = p.si[t][e];
    int dg = p.cntOff[t] + p.di[t][e];
    int pos = atomicAdd(&g_head[dg], 1);
    g_eSrc[pos] = s;
}

// ---------------------------------------------------------------------------
// Gather-aggregate: one warp per dst row. Register accumulation over the
// CSR neighbor list, single plain store; mean (1/deg) folded in here.
// ---------------------------------------------------------------------------
struct GathParams {
    const float* xs[5];
    int rowPrefix[6];
};

__global__ void gather_kernel(GathParams p) {
    long long gt = (long long)blockIdx.x * blockDim.x + threadIdx.x;
    int r = (int)(gt >> 5);
    int c = (int)(gt & 31);
    if (r >= p.rowPrefix[5]) return;
    int t = 0;
    while (r >= p.rowPrefix[t + 1]) t++;
    const float* xsrc = p.xs[t];

    int j0 = g_rowStart[r];
    int j1 = g_rowStart[r + 1];
    float4 acc = make_float4(0.f, 0.f, 0.f, 0.f);
    for (int j = j0; j < j1; j++) {
        int s = g_eSrc[j];
        float4 v = ((const float4*)(xsrc + (size_t)s * D))[c];
        acc.x += v.x; acc.y += v.y; acc.z += v.z; acc.w += v.w;
    }
    float invd = 1.f / fmaxf((float)(j1 - j0), 1.f);
    acc.x *= invd; acc.y *= invd; acc.z *= invd; acc.w *= invd;
    ((float4*)g_agg)[(size_t)r * 32 + c] = acc;
}

// ---------------------------------------------------------------------------
// Mega-GEMM (tf32 mma.sync.m16n8k8):
//   C[M x 128] = [x_dst | agg] (M x 256) @ [wl^T ; wr^T]
// then + bias, row L2-normalize, red.v2-accumulate into zeroed out.
// ---------------------------------------------------------------------------
__device__ __forceinline__ void mma_tf32(float* c, const unsigned* a,
                                         unsigned b0, unsigned b1) {
    asm volatile(
        "mma.sync.aligned.m16n8k8.row.col.f32.tf32.tf32.f32 "
        "{%0,%1,%2,%3}, {%4,%5,%6,%7}, {%8,%9}, {%0,%1,%2,%3};"
        : "+f"(c[0]), "+f"(c[1]), "+f"(c[2]), "+f"(c[3])
        : "r"(a[0]), "r"(a[1]), "r"(a[2]), "r"(a[3]), "r"(b0), "r"(b1));
}

struct GemmParams {
    const float* xd[5];
    const float* bias[5];
    float*       out[5];
    size_t aggOff[5];
    int    nd[5];
    int    blkPrefix[6];
};

__global__ __launch_bounds__(256) void gemm_kernel(GemmParams p) {
    int b = blockIdx.x;
    int t = 0;
    while (b >= p.blkPrefix[t + 1]) t++;
    int rowBase = (b - p.blkPrefix[t]) * 128;
    int n_dst = p.nd[t];
    const float* xd  = p.xd[t];
    const float* agg = g_agg + p.aggOff[t];
    const unsigned* Bl = g_B + (size_t)t * 32768;
    const unsigned* Br = Bl + 16384;

    __shared__ unsigned As[128][36];
    __shared__ unsigned Bs[128][36];
    __shared__ float rowsum[2][128];

    int tid = threadIdx.x;
    int wid = tid >> 5, lane = tid & 31;
    int warpM = wid & 3, warpN = wid >> 2;
    int lq = lane & 3;
    int lr = lane >> 2;

    float acc[2][8][4];
#pragma unroll
    for (int mt = 0; mt < 2; mt++)
#pragma unroll
        for (int nt = 0; nt < 8; nt++)
#pragma unroll
            for (int r = 0; r < 4; r++) acc[mt][nt][r] = 0.f;

    for (int kt = 0; kt < 8; kt++) {
        bool isAgg = (kt >= 4);
        int kLocal = (kt & 3) * 32;
        const float* srcA = isAgg ? agg : xd;
        const unsigned* Bp = isAgg ? Br : Bl;

        if (kt) __syncthreads();

#pragma unroll
        for (int it = 0; it < 4; it++) {
            int f = it * 256 + tid;
            int r = f >> 3;
            int c4 = (f & 7) * 4;
            int gr = rowBase + r;
            float4 v = make_float4(0.f, 0.f, 0.f, 0.f);
            if (gr < n_dst)
                v = *(const float4*)(srcA + (size_t)gr * D + kLocal + c4);
            unsigned u0, u1, u2, u3;
            asm("cvt.rna.tf32.f32 %0, %1;" : "=r"(u0) : "f"(v.x));
            asm("cvt.rna.tf32.f32 %0, %1;" : "=r"(u1) : "f"(v.y));
            asm("cvt.rna.tf32.f32 %0, %1;" : "=r"(u2) : "f"(v.z));
            asm("cvt.rna.tf32.f32 %0, %1;" : "=r"(u3) : "f"(v.w));
            As[r][c4 + 0] = u0; As[r][c4 + 1] = u1;
            As[r][c4 + 2] = u2; As[r][c4 + 3] = u3;
        }
#pragma unroll
        for (int it = 0; it < 4; it++) {
            int f = it * 256 + tid;
            int r = f >> 3;
            int c4 = (f & 7) * 4;
            uint4 u = *(const uint4*)(Bp + (size_t)r * D + kLocal + c4);
            Bs[r][c4 + 0] = u.x; Bs[r][c4 + 1] = u.y;
            Bs[r][c4 + 2] = u.z; Bs[r][c4 + 3] = u.w;
        }
        __syncthreads();

#pragma unroll
        for (int k8 = 0; k8 < 4; k8++) {
            int kq = k8 * 8 + lq;
            unsigned a[2][4];
#pragma unroll
            for (int mt = 0; mt < 2; mt++) {
                int r0 = warpM * 32 + mt * 16 + lr;
                a[mt][0] = As[r0][kq];
                a[mt][1] = As[r0 + 8][kq];
                a[mt][2] = As[r0][kq + 4];
                a[mt][3] = As[r0 + 8][kq + 4];
            }
#pragma unroll
            for (int nt = 0; nt < 8; nt++) {
                int n0 = warpN * 64 + nt * 8 + lr;
                unsigned b0 = Bs[n0][kq];
                unsigned b1 = Bs[n0][kq + 4];
                mma_tf32(acc[0][nt], a[0], b0, b1);
                mma_tf32(acc[1][nt], a[1], b0, b1);
            }
        }
    }

    const float* bias = p.bias[t];
    float biasv[16];
#pragma unroll
    for (int nt = 0; nt < 8; nt++) {
        float2 bb = *(const float2*)(bias + warpN * 64 + nt * 8 + 2 * lq);
        biasv[2 * nt] = bb.x;
        biasv[2 * nt + 1] = bb.y;
    }

    float ps[2][2] = {{0.f, 0.f}, {0.f, 0.f}};
#pragma unroll
    for (int mt = 0; mt < 2; mt++)
#pragma unroll
        for (int nt = 0; nt < 8; nt++) {
            acc[mt][nt][0] += biasv[2 * nt];
            acc[mt][nt][1] += biasv[2 * nt + 1];
            acc[mt][nt][2] += biasv[2 * nt];
            acc[mt][nt][3] += biasv[2 * nt + 1];
            ps[mt][0] += acc[mt][nt][0] * acc[mt][nt][0]
                       + acc[mt][nt][1] * acc[mt][nt][1];
            ps[mt][1] += acc[mt][nt][2] * acc[mt][nt][2]
                       + acc[mt][nt][3] * acc[mt][nt][3];
        }
#pragma unroll
    for (int mt = 0; mt < 2; mt++)
#pragma unroll
        for (int h = 0; h < 2; h++) {
            float v = ps[mt][h];
            v += __shfl_xor_sync(0xffffffffu, v, 1);
            v += __shfl_xor_sync(0xffffffffu, v, 2);
            if (lq == 0)
                rowsum[warpN][warpM * 32 + mt * 16 + h * 8 + lr] = v;
        }
    __syncthreads();

    float* outp = p.out[t];
#pragma unroll
    for (int mt = 0; mt < 2; mt++)
#pragma unroll
        for (int h = 0; h < 2; h++) {
            int rloc = warpM * 32 + mt * 16 + h * 8 + lr;
            int gr = rowBase + rloc;
            if (gr >= n_dst) continue;
            float ss = rowsum[0][rloc] + rowsum[1][rloc];
            float inv = 1.f / fmaxf(sqrtf(ss), 1e-12f);
#pragma unroll
            for (int nt = 0; nt < 8; nt++) {
                float vx = acc[mt][nt][h * 2 + 0] * inv;
                float vy = acc[mt][nt][h * 2 + 1] * inv;
                float* pp = outp + (size_t)gr * D + warpN * 64 + nt * 8 + 2 * lq;
                asm volatile("red.global.add.v2.f32 [%0], {%1,%2};"
                             :: "l"(pp), "f"(vx), "f"(vy) : "memory");
            }
        }
}

// ---------------------------------------------------------------------------
// Host orchestration (all stream 0, graph-capturable)
// ---------------------------------------------------------------------------
extern "C" void kernel_launch(void* const* d_in, const int* in_sizes, int n_in,
                              void* d_out, int out_size) {
    const float* xa = (const float*)d_in[0];
    const float* xe = (const float*)d_in[1];
    const float* xf = (const float*)d_in[2];
    int NA = in_sizes[0] / D;
    int NE = in_sizes[1] / D;
    int NF = in_sizes[2] / D;

    int* degPtr;
    cudaGetSymbolAddress((void**)&degPtr, g_deg);

    float* out = (float*)d_out;
    float* out_a = out;
    float* out_e = out + (size_t)NA * D;
    float* out_f = out + (size_t)(NA + NE) * D;

    // EDGE_TYPES: (a->e), (a->f), (e->a), (e->f), (f->e)
    const float* xs[5] = {xa, xa, xe, xe, xf};
    const float* xd[5] = {xe, xf, xa, xf, xe};
    int nd[5]          = {NE, NF, NA, NF, NE};
    float* od[5]       = {out_e, out_f, out_a, out_f, out_e};

    PrepParams pp;
    EdgeParams ep;
    GathParams gap;
    GemmParams gp;

    int rowCum = 0, eCum = 0, blkCum = 0;
    ep.ePrefix[0] = 0;
    gap.rowPrefix[0] = 0;
    gp.blkPrefix[0] = 0;
    for (int t = 0; t < 5; t++) {
        pp.wl[t] = (const float*)d_in[13 + 3 * t];
        pp.wr[t] = (const float*)d_in[15 + 3 * t];
        ep.si[t] = (const int*)d_in[3 + 2 * t];
        ep.di[t] = (const int*)d_in[4 + 2 * t];
        ep.cntOff[t] = rowCum;
        gap.xs[t] = xs[t];
        gp.xd[t] = xd[t];
        gp.bias[t] = (const float*)d_in[14 + 3 * t];
        gp.out[t] = od[t];
        gp.aggOff[t] = (size_t)rowCum * D;
        gp.nd[t] = nd[t];
        rowCum += nd[t];
        eCum += in_sizes[3 + 2 * t];
        blkCum += (nd[t] + 127) / 128;
        ep.ePrefix[t + 1] = eCum;
        gap.rowPrefix[t + 1] = rowCum;
        gp.blkPrefix[t + 1] = blkCum;
    }
    int R = rowCum;
    int nbScan = (R + 4095) / 4096;

    // zero degree histogram and output (RED-accumulated)
    cudaMemsetAsync(degPtr, 0, (size_t)R * sizeof(int), 0);
    cudaMemsetAsync(d_out, 0, (size_t)out_size * sizeof(float), 0);

    prep_kernel<<<(5 * 2 * D * D) / 256, 256>>>(pp);

    hist_kernel<<<(eCum + 255) / 256, 256>>>(ep);
    scan1_kernel<<<nbScan, 1024>>>(R);
    scan2_kernel<<<1, 32>>>(nbScan);
    scan3_kernel<<<(R + 256) / 256, 256>>>(R, nbScan);
    fill_kernel<<<(eCum + 255) / 256, 256>>>(ep);

    long long gthr = (long long)R * 32;
    gather_kernel<<<(int)((gthr + 255) / 256), 256>>>(gap);

    gemm_kernel<<<blkCum, 256>>>(gp);
}